// round 2
// baseline (speedup 1.0000x reference)
#include <cuda_runtime.h>

#define FULLMASK 0xffffffffu
#define B_ 2
#define N_ 8192
#define K_ 16
#define C_ 32

static __device__ __forceinline__ float finf() { return __int_as_float(0x7f800000); }

// ---- scratch (device globals; no allocation allowed) ----
__device__ int   g_knn[B_ * N_ * K_];        // 2 MB
__device__ float g_lt [B_ * N_ * 96];        // 6 MB
__device__ float g_part[512 * 8];
__device__ float g_stats[8];                 // mean[4], rstd[4]

__device__ __forceinline__ float warp_sum(float v) {
#pragma unroll
    for (int off = 16; off; off >>= 1)
        v += __shfl_xor_sync(FULLMASK, v, off);
    return v;
}

// =====================================================================
// Kernel 1: KNN — warp per query, 32 candidates per step, ballot-insert
// =====================================================================
__global__ __launch_bounds__(1024) void knn_kernel(const float4* __restrict__ xytp)
{
    __shared__ float4 tile[2048];             // 32 KB
    const int b    = blockIdx.y;
    const int warp = threadIdx.x >> 5;
    const int lane = threadIdx.x & 31;
    const int q    = blockIdx.x * 32 + warp;
    const float4* xp = xytp + (size_t)b * N_;

    const float4 qp = xp[q];

    // top-16 list distributed in lanes 0..15
    float ld   = finf();
    int   li   = 0;
    float cmax = finf();

    for (int t = 0; t < 4; ++t) {
        const int base = t * 2048;
        __syncthreads();
        for (int i = threadIdx.x; i < 2048; i += 1024) {
            float4 v = xp[base + i];
            v.w = fmaf(v.z, v.z, fmaf(v.y, v.y, v.x * v.x));  // |p|^2 (first 3 dims)
            tile[i] = v;
        }
        __syncthreads();

        for (int s = 0; s < 64; ++s) {
            const float4 cv = tile[s * 32 + lane];
            const int    j  = base + s * 32 + lane;
            float dot  = fmaf(qp.z, cv.z, fmaf(qp.y, cv.y, qp.x * cv.x));
            float dist = fmaf(-2.f, dot, cv.w);   // |q|^2 const dropped: same ordering
            unsigned bal = __ballot_sync(FULLMASK, dist < cmax);
            while (bal) {
                const int src = __ffs(bal) - 1;
                bal &= bal - 1;
                const float dv = __shfl_sync(FULLMASK, dist, src);
                const int   iv = __shfl_sync(FULLMASK, j,    src);
                if (dv < cmax) {   // recheck: cmax tightens inside loop
                    // argmax over lanes 0..15 (ties -> lowest lane, keeps all lanes agreeing)
                    float v  = (lane < 16) ? ld : -finf();
                    int   al = lane;
#pragma unroll
                    for (int off = 8; off; off >>= 1) {
                        const float ov = __shfl_xor_sync(FULLMASK, v,  off);
                        const int   oa = __shfl_xor_sync(FULLMASK, al, off);
                        if (ov > v || (ov == v && oa < al)) { v = ov; al = oa; }
                    }
                    if (lane == al) { ld = dv; li = iv; }
                    float m = (lane < 16) ? ld : -finf();
#pragma unroll
                    for (int off = 8; off; off >>= 1)
                        m = fmaxf(m, __shfl_xor_sync(FULLMASK, m, off));
                    cmax = __shfl_sync(FULLMASK, m, 0);
                }
            }
        }
    }
    if (lane < 16)
        g_knn[((size_t)b * N_ + q) * K_ + lane] = li;
}

// =====================================================================
// Kernel 2: lt = features @ lt_w^T + lt_b   (thread per point)
// =====================================================================
__global__ __launch_bounds__(256) void lt_kernel(const float* __restrict__ features,
                                                 const float* __restrict__ lt_w,
                                                 const float* __restrict__ lt_b)
{
    __shared__ float w[96 * 32];
    __shared__ float bias[96];
    for (int i = threadIdx.x; i < 96 * 32; i += 256) w[i] = lt_w[i];
    if (threadIdx.x < 96) bias[threadIdx.x] = lt_b[threadIdx.x];
    __syncthreads();

    const int p = blockIdx.x * 256 + threadIdx.x;   // < 16384
    float4 f4[8];
    const float4* fr = (const float4*)(features + (size_t)p * C_);
#pragma unroll
    for (int i = 0; i < 8; ++i) f4[i] = fr[i];

    float* outp = g_lt + (size_t)p * 96;
#pragma unroll 4
    for (int o = 0; o < 96; ++o) {
        float a = bias[o];
        const float4* wr = (const float4*)(w + o * 32);
#pragma unroll
        for (int i = 0; i < 8; ++i) {
            const float4 wv = wr[i];
            a = fmaf(f4[i].x, wv.x, a);
            a = fmaf(f4[i].y, wv.y, a);
            a = fmaf(f4[i].z, wv.z, a);
            a = fmaf(f4[i].w, wv.w, a);
        }
        outp[o] = a;
    }
}

// =====================================================================
// Kernel 3: position-encoder global stats pass 1 (per-block partials)
// =====================================================================
__global__ __launch_bounds__(256) void pe_stats_kernel(const float4* __restrict__ xytp,
                                                       const float* __restrict__ pe_w1,
                                                       const float* __restrict__ pe_b1)
{
    __shared__ float sm[8 * 8];
    float w1[16], b1[4];
#pragma unroll
    for (int i = 0; i < 16; ++i) w1[i] = pe_w1[i];
#pragma unroll
    for (int f = 0; f < 4; ++f) b1[f] = pe_b1[f];

    float acc[8];
#pragma unroll
    for (int i = 0; i < 8; ++i) acc[i] = 0.f;

    const int total = B_ * N_ * K_;   // 262144
    for (int e = blockIdx.x * 256 + threadIdx.x; e < total; e += gridDim.x * 256) {
        const int j  = g_knn[e];
        const int pk = e >> 4;          // b*N + n
        const int b  = pk >> 13;
        const float4 q  = xytp[pk];
        const float4 nb = xytp[b * N_ + j];
        const float r0 = q.x - nb.x, r1 = q.y - nb.y, r2 = q.z - nb.z, r3 = q.w - nb.w;
#pragma unroll
        for (int f = 0; f < 4; ++f) {
            float h = b1[f];
            h = fmaf(r0, w1[f * 4 + 0], h);
            h = fmaf(r1, w1[f * 4 + 1], h);
            h = fmaf(r2, w1[f * 4 + 2], h);
            h = fmaf(r3, w1[f * 4 + 3], h);
            acc[f]     += h;
            acc[4 + f]  = fmaf(h, h, acc[4 + f]);
        }
    }
#pragma unroll
    for (int i = 0; i < 8; ++i) acc[i] = warp_sum(acc[i]);
    const int warp = threadIdx.x >> 5, lane = threadIdx.x & 31;
    if (lane == 0) {
#pragma unroll
        for (int i = 0; i < 8; ++i) sm[warp * 8 + i] = acc[i];
    }
    __syncthreads();
    if (threadIdx.x < 8) {
        float t = 0.f;
#pragma unroll
        for (int w = 0; w < 8; ++w) t += sm[w * 8 + threadIdx.x];
        g_part[blockIdx.x * 8 + threadIdx.x] = t;
    }
}

// =====================================================================
// Kernel 4: finalize stats (deterministic fixed-order reduce)
// =====================================================================
__global__ void pe_finalize_kernel()
{
    __shared__ float tot[8];
    if (threadIdx.x < 8) {
        float s = 0.f;
        for (int i = 0; i < 512; ++i) s += g_part[i * 8 + threadIdx.x];
        tot[threadIdx.x] = s;
    }
    __syncthreads();
    if (threadIdx.x < 4) {
        const float invc = 1.f / (float)(B_ * N_ * K_);
        const float mean = tot[threadIdx.x] * invc;
        const float var  = fmaf(tot[4 + threadIdx.x], invc, -mean * mean);
        g_stats[threadIdx.x]     = mean;
        g_stats[4 + threadIdx.x] = rsqrtf(var + 1e-5f);
    }
}

// =====================================================================
// Kernel 5: fused main — warp per point, lane = channel
// =====================================================================
__global__ __launch_bounds__(256) void main_kernel(const float4* __restrict__ xytp,
                                                   const float* __restrict__ pe_w1,
                                                   const float* __restrict__ pe_b1,
                                                   const float* __restrict__ pe_gamma,
                                                   const float* __restrict__ pe_beta,
                                                   const float* __restrict__ pe_w2,
                                                   const float* __restrict__ pe_b2,
                                                   const float* __restrict__ ln_gamma,
                                                   const float* __restrict__ ln_beta,
                                                   float* __restrict__ out)
{
    const int warp = threadIdx.x >> 5;
    const int lane = threadIdx.x & 31;
    const int p    = blockIdx.x * 8 + warp;     // point id in [0, 16384)
    const int b    = p >> 13;

    float w1[16], b1v[4], mean[4], rstd[4], gam[4], bet[4], w2a[4];
#pragma unroll
    for (int i = 0; i < 16; ++i) w1[i] = pe_w1[i];
#pragma unroll
    for (int f = 0; f < 4; ++f) {
        b1v[f]  = pe_b1[f];
        mean[f] = g_stats[f];
        rstd[f] = g_stats[4 + f];
        gam[f]  = pe_gamma[f];
        bet[f]  = pe_beta[f];
    }
    {
        const float4 w2 = ((const float4*)pe_w2)[lane];
        w2a[0] = w2.x; w2a[1] = w2.y; w2a[2] = w2.z; w2a[3] = w2.w;
    }
    const float b2 = pe_b2[lane];
    const float lg = ln_gamma[lane];
    const float lb = ln_beta[lane];

    const float  varphi = g_lt[(size_t)p * 96 + lane];
    const float4 q      = xytp[p];
    const int    myidx  = g_knn[(size_t)p * K_ + (lane & 15)];

    float lgt[16], av[16];
#pragma unroll
    for (int k = 0; k < 16; ++k) {
        const int j = __shfl_sync(FULLMASK, myidx, k);
        const float4 nb = xytp[(size_t)b * N_ + j];
        const float r0 = q.x - nb.x, r1 = q.y - nb.y, r2 = q.z - nb.z, r3 = q.w - nb.w;

        float del = b2;
#pragma unroll
        for (int f = 0; f < 4; ++f) {
            float h = b1v[f];
            h = fmaf(r0, w1[f * 4 + 0], h);
            h = fmaf(r1, w1[f * 4 + 1], h);
            h = fmaf(r2, w1[f * 4 + 2], h);
            h = fmaf(r3, w1[f * 4 + 3], h);
            float u = (h - mean[f]) * rstd[f];
            u = fmaf(u, gam[f], bet[f]);
            u = fmaxf(u, 0.f);
            del = fmaf(u, w2a[f], del);
        }

        const size_t row = ((size_t)b * N_ + j) * 96;
        const float psi   = g_lt[row + 32 + lane];
        const float alpha = g_lt[row + 64 + lane];

        const float pre = (varphi - psi) + del;
        const float s1  = warp_sum(pre);
        const float s2  = warp_sum(pre * pre);
        const float mu  = s1 * (1.f / 32.f);
        const float var = fmaf(s2, 1.f / 32.f, -mu * mu);
        const float rs  = rsqrtf(var + 1e-5f);
        lgt[k] = fmaf((pre - mu) * rs, lg, lb);
        av[k]  = alpha + del;
    }

    float m = -finf();
#pragma unroll
    for (int k = 0; k < 16; ++k) m = fmaxf(m, lgt[k]);
    const float inv_scale = 0.17677669529663687f;   // 1/sqrt(32)
    float se = 0.f, acc = 0.f;
#pragma unroll
    for (int k = 0; k < 16; ++k) {
        const float e = __expf((lgt[k] - m) * inv_scale);
        se  += e;
        acc  = fmaf(e, av[k], acc);
    }
    out[(size_t)p * C_ + lane] = acc / se;
}

// =====================================================================
// Launch
// =====================================================================
extern "C" void kernel_launch(void* const* d_in, const int* in_sizes, int n_in,
                              void* d_out, int out_size)
{
    const float* xytp     = (const float*)d_in[0];
    const float* features = (const float*)d_in[1];
    const float* pe_w1    = (const float*)d_in[2];
    const float* pe_b1    = (const float*)d_in[3];
    const float* pe_gamma = (const float*)d_in[4];
    const float* pe_beta  = (const float*)d_in[5];
    const float* pe_w2    = (const float*)d_in[6];
    const float* pe_b2    = (const float*)d_in[7];
    const float* lt_w     = (const float*)d_in[8];
    const float* lt_b     = (const float*)d_in[9];
    const float* ln_gamma = (const float*)d_in[10];
    const float* ln_beta  = (const float*)d_in[11];
    float* out = (float*)d_out;

    knn_kernel<<<dim3(N_ / 32, B_), 1024>>>((const float4*)xytp);
    lt_kernel<<<(B_ * N_) / 256, 256>>>(features, lt_w, lt_b);
    pe_stats_kernel<<<512, 256>>>((const float4*)xytp, pe_w1, pe_b1);
    pe_finalize_kernel<<<1, 32>>>();
    main_kernel<<<(B_ * N_) / 8, 256>>>((const float4*)xytp, pe_w1, pe_b1,
                                        pe_gamma, pe_beta, pe_w2, pe_b2,
                                        ln_gamma, ln_beta, out);
}

// round 3
// speedup vs baseline: 1.6283x; 1.6283x over previous
#include <cuda_runtime.h>

#define FULLMASK 0xffffffffu
#define B_ 2
#define N_ 8192
#define K_ 16
#define C_ 32
#define QPB 16                      // queries per knn block
#define KNN_BLOCKS (N_ / QPB)       // 512 per batch

static __device__ __forceinline__ float finf() { return __int_as_float(0x7f800000); }

// ---- scratch (device globals; no allocation allowed) ----
__device__ int   g_knn[B_ * N_ * K_];              // 2 MB
__device__ float g_lt [B_ * N_ * 96];              // 6 MB
__device__ float g_part[B_ * KNN_BLOCKS * 8];      // 1024 partial sets
__device__ float g_stats[8];                       // mean[4], rstd[4]

__device__ __forceinline__ float warp_sum(float v) {
#pragma unroll
    for (int off = 16; off; off >>= 1)
        v += __shfl_xor_sync(FULLMASK, v, off);
    return v;
}

// sorted top-16 list in lanes 0..15 (ascending); stable insert
__device__ __forceinline__ void insert16(float dv, int iv, int lane,
                                         float& ld, int& li, float& cmax)
{
    const unsigned m = __ballot_sync(FULLMASK, ld <= dv) & 0xFFFFu;
    const int pos = __popc(m);                       // after equals -> stable
    const float pld = __shfl_up_sync(FULLMASK, ld, 1);
    const int   pli = __shfl_up_sync(FULLMASK, li, 1);
    if (lane > pos && lane < 16) { ld = pld; li = pli; }
    if (lane == pos)             { ld = dv;  li = iv;  }
    cmax = __shfl_sync(FULLMASK, ld, 15);
}

// =====================================================================
// Kernel 1: KNN (warp/query, sorted-list insert) + fused PE-stats partials
// =====================================================================
__global__ __launch_bounds__(512) void knn_kernel(const float4* __restrict__ xytp,
                                                  const float* __restrict__ pe_w1,
                                                  const float* __restrict__ pe_b1)
{
    __shared__ float4 tile[2048];           // 32 KB
    __shared__ float  sred[QPB * 8];
    const int b    = blockIdx.y;
    const int tid  = threadIdx.x;
    const int warp = tid >> 5;
    const int lane = tid & 31;
    const int q    = blockIdx.x * QPB + warp;
    const float4* xp = xytp + (size_t)b * N_;

    const float4 qp = xp[q];

    float ld   = finf();
    int   li   = 0;
    float cmax = finf();

    for (int t = 0; t < 4; ++t) {
        const int base = t * 2048;
        __syncthreads();
        for (int i = tid; i < 2048; i += 512) {
            const float4 v = xp[base + i];
            const float n2 = fmaf(v.z, v.z, fmaf(v.y, v.y, v.x * v.x));
            tile[i] = make_float4(-2.f * v.x, -2.f * v.y, -2.f * v.z, n2);
        }
        __syncthreads();

#pragma unroll 4
        for (int s = 0; s < 32; ++s) {
            const float4 c0 = tile[s * 64 + lane];
            const float4 c1 = tile[s * 64 + 32 + lane];
            const float d0 = fmaf(qp.x, c0.x, fmaf(qp.y, c0.y, fmaf(qp.z, c0.z, c0.w)));
            const float d1 = fmaf(qp.x, c1.x, fmaf(qp.y, c1.y, fmaf(qp.z, c1.z, c1.w)));
            const bool p0 = d0 < cmax;
            const bool p1 = d1 < cmax;
            if (__ballot_sync(FULLMASK, p0 | p1)) {
                unsigned b0 = __ballot_sync(FULLMASK, p0);
                while (b0) {
                    const int src = __ffs(b0) - 1; b0 &= b0 - 1;
                    const float dv = __shfl_sync(FULLMASK, d0, src);
                    if (dv < cmax)
                        insert16(dv, base + s * 64 + src, lane, ld, li, cmax);
                }
                unsigned b1m = __ballot_sync(FULLMASK, p1);
                while (b1m) {
                    const int src = __ffs(b1m) - 1; b1m &= b1m - 1;
                    const float dv = __shfl_sync(FULLMASK, d1, src);
                    if (dv < cmax)
                        insert16(dv, base + s * 64 + 32 + src, lane, ld, li, cmax);
                }
            }
        }
    }
    if (lane < 16)
        g_knn[((size_t)b * N_ + q) * K_ + lane] = li;

    // ---- fused position-encoder stats partials (h-sum, h²-sum per channel) ----
    float acc[8];
#pragma unroll
    for (int i = 0; i < 8; ++i) acc[i] = 0.f;
    if (lane < 16) {
        const float4 nb = xp[li];
        const float r0 = qp.x - nb.x, r1 = qp.y - nb.y, r2 = qp.z - nb.z, r3 = qp.w - nb.w;
#pragma unroll
        for (int f = 0; f < 4; ++f) {
            float h = pe_b1[f];
            h = fmaf(r0, pe_w1[f * 4 + 0], h);
            h = fmaf(r1, pe_w1[f * 4 + 1], h);
            h = fmaf(r2, pe_w1[f * 4 + 2], h);
            h = fmaf(r3, pe_w1[f * 4 + 3], h);
            acc[f]     = h;
            acc[4 + f] = h * h;
        }
    }
#pragma unroll
    for (int i = 0; i < 8; ++i) acc[i] = warp_sum(acc[i]);
    if (lane == 0) {
#pragma unroll
        for (int i = 0; i < 8; ++i) sred[warp * 8 + i] = acc[i];
    }
    __syncthreads();
    if (tid < 8) {
        float s = 0.f;
#pragma unroll
        for (int w = 0; w < QPB; ++w) s += sred[w * 8 + tid];
        g_part[((size_t)blockIdx.y * KNN_BLOCKS + blockIdx.x) * 8 + tid] = s;
    }
}

// =====================================================================
// Kernel 2: lt = features @ lt_w^T + lt_b   (thread per point)
// =====================================================================
__global__ __launch_bounds__(256) void lt_kernel(const float* __restrict__ features,
                                                 const float* __restrict__ lt_w,
                                                 const float* __restrict__ lt_b)
{
    __shared__ float w[96 * 32];
    __shared__ float bias[96];
    for (int i = threadIdx.x; i < 96 * 32; i += 256) w[i] = lt_w[i];
    if (threadIdx.x < 96) bias[threadIdx.x] = lt_b[threadIdx.x];
    __syncthreads();

    const int p = blockIdx.x * 256 + threadIdx.x;
    float4 f4[8];
    const float4* fr = (const float4*)(features + (size_t)p * C_);
#pragma unroll
    for (int i = 0; i < 8; ++i) f4[i] = fr[i];

    float* outp = g_lt + (size_t)p * 96;
#pragma unroll 4
    for (int o = 0; o < 96; ++o) {
        float a = bias[o];
        const float4* wr = (const float4*)(w + o * 32);
#pragma unroll
        for (int i = 0; i < 8; ++i) {
            const float4 wv = wr[i];
            a = fmaf(f4[i].x, wv.x, a);
            a = fmaf(f4[i].y, wv.y, a);
            a = fmaf(f4[i].z, wv.z, a);
            a = fmaf(f4[i].w, wv.w, a);
        }
        outp[o] = a;
    }
}

// =====================================================================
// Kernel 3: finalize stats (parallel, fixed-order => deterministic)
// =====================================================================
__global__ __launch_bounds__(256) void pe_finalize_kernel()
{
    __shared__ float red[32 * 8];
    __shared__ float tot8[8];
    const int t = threadIdx.x;          // 256
    const int ch = t & 7, grp = t >> 3; // 32 groups of 32 partials
    float s = 0.f;
    const int base = grp * 32;
    for (int i = 0; i < 32; ++i) s += g_part[(base + i) * 8 + ch];
    red[grp * 8 + ch] = s;
    __syncthreads();
    if (t < 8) {
        float tt = 0.f;
        for (int g = 0; g < 32; ++g) tt += red[g * 8 + t];
        tot8[t] = tt;
    }
    __syncthreads();
    if (t < 4) {
        const float invc = 1.f / (float)(B_ * N_ * K_);
        const float mean = tot8[t] * invc;
        const float var  = fmaf(tot8[4 + t], invc, -mean * mean);
        g_stats[t]     = mean;
        g_stats[4 + t] = rsqrtf(var + 1e-5f);
    }
}

// =====================================================================
// Kernel 4: fused main — warp per point, lane = channel
// =====================================================================
__global__ __launch_bounds__(256) void main_kernel(const float4* __restrict__ xytp,
                                                   const float* __restrict__ pe_w1,
                                                   const float* __restrict__ pe_b1,
                                                   const float* __restrict__ pe_gamma,
                                                   const float* __restrict__ pe_beta,
                                                   const float* __restrict__ pe_w2,
                                                   const float* __restrict__ pe_b2,
                                                   const float* __restrict__ ln_gamma,
                                                   const float* __restrict__ ln_beta,
                                                   float* __restrict__ out)
{
    const int warp = threadIdx.x >> 5;
    const int lane = threadIdx.x & 31;
    const int p    = blockIdx.x * 8 + warp;
    const int b    = p >> 13;

    float w1[16], b1v[4], mean[4], rstd[4], gam[4], bet[4], w2a[4];
#pragma unroll
    for (int i = 0; i < 16; ++i) w1[i] = pe_w1[i];
#pragma unroll
    for (int f = 0; f < 4; ++f) {
        b1v[f]  = pe_b1[f];
        mean[f] = g_stats[f];
        rstd[f] = g_stats[4 + f];
        gam[f]  = pe_gamma[f];
        bet[f]  = pe_beta[f];
    }
    {
        const float4 w2 = ((const float4*)pe_w2)[lane];
        w2a[0] = w2.x; w2a[1] = w2.y; w2a[2] = w2.z; w2a[3] = w2.w;
    }
    const float b2 = pe_b2[lane];
    const float lg = ln_gamma[lane];
    const float lb = ln_beta[lane];

    const float  varphi = g_lt[(size_t)p * 96 + lane];
    const float4 q      = xytp[p];
    const int    myidx  = g_knn[(size_t)p * K_ + (lane & 15)];

    float lgt[16], av[16];
#pragma unroll
    for (int k = 0; k < 16; ++k) {
        const int j = __shfl_sync(FULLMASK, myidx, k);
        const float4 nb = xytp[(size_t)b * N_ + j];
        const float r0 = q.x - nb.x, r1 = q.y - nb.y, r2 = q.z - nb.z, r3 = q.w - nb.w;

        float del = b2;
#pragma unroll
        for (int f = 0; f < 4; ++f) {
            float h = b1v[f];
            h = fmaf(r0, w1[f * 4 + 0], h);
            h = fmaf(r1, w1[f * 4 + 1], h);
            h = fmaf(r2, w1[f * 4 + 2], h);
            h = fmaf(r3, w1[f * 4 + 3], h);
            float u = (h - mean[f]) * rstd[f];
            u = fmaf(u, gam[f], bet[f]);
            u = fmaxf(u, 0.f);
            del = fmaf(u, w2a[f], del);
        }

        const size_t row = ((size_t)b * N_ + j) * 96;
        const float psi   = g_lt[row + 32 + lane];
        const float alpha = g_lt[row + 64 + lane];

        const float pre = (varphi - psi) + del;
        const float s1  = warp_sum(pre);
        const float s2  = warp_sum(pre * pre);
        const float mu  = s1 * (1.f / 32.f);
        const float var = fmaf(s2, 1.f / 32.f, -mu * mu);
        const float rs  = rsqrtf(var + 1e-5f);
        lgt[k] = fmaf((pre - mu) * rs, lg, lb);
        av[k]  = alpha + del;
    }

    float m = -finf();
#pragma unroll
    for (int k = 0; k < 16; ++k) m = fmaxf(m, lgt[k]);
    const float inv_scale = 0.17677669529663687f;   // 1/sqrt(32)
    float se = 0.f, acc = 0.f;
#pragma unroll
    for (int k = 0; k < 16; ++k) {
        const float e = __expf((lgt[k] - m) * inv_scale);
        se  += e;
        acc  = fmaf(e, av[k], acc);
    }
    out[(size_t)p * C_ + lane] = acc / se;
}

// =====================================================================
// Launch
// =====================================================================
extern "C" void kernel_launch(void* const* d_in, const int* in_sizes, int n_in,
                              void* d_out, int out_size)
{
    const float* xytp     = (const float*)d_in[0];
    const float* features = (const float*)d_in[1];
    const float* pe_w1    = (const float*)d_in[2];
    const float* pe_b1    = (const float*)d_in[3];
    const float* pe_gamma = (const float*)d_in[4];
    const float* pe_beta  = (const float*)d_in[5];
    const float* pe_w2    = (const float*)d_in[6];
    const float* pe_b2    = (const float*)d_in[7];
    const float* lt_w     = (const float*)d_in[8];
    const float* lt_b     = (const float*)d_in[9];
    const float* ln_gamma = (const float*)d_in[10];
    const float* ln_beta  = (const float*)d_in[11];
    float* out = (float*)d_out;

    knn_kernel<<<dim3(KNN_BLOCKS, B_), 512>>>((const float4*)xytp, pe_w1, pe_b1);
    lt_kernel<<<(B_ * N_) / 256, 256>>>(features, lt_w, lt_b);
    pe_finalize_kernel<<<1, 256>>>();
    main_kernel<<<(B_ * N_) / 8, 256>>>((const float4*)xytp, pe_w1, pe_b1,
                                        pe_gamma, pe_beta, pe_w2, pe_b2,
                                        ln_gamma, ln_beta, out);
}

// round 4
// speedup vs baseline: 1.6390x; 1.0066x over previous
#include <cuda_runtime.h>

#define FULLMASK 0xffffffffu
#define B_ 2
#define N_ 8192
#define K_ 16
#define C_ 32
#define QPB 32                      // queries per knn block (16 warps x 2)
#define KNN_BLOCKS (N_ / QPB)       // 256 per batch
#define NPART (B_ * KNN_BLOCKS)     // 512 partial sets

static __device__ __forceinline__ float finf() { return __int_as_float(0x7f800000); }

// ---- scratch (device globals; no allocation allowed) ----
__device__ int   g_knn[B_ * N_ * K_];              // 2 MB
__device__ float g_lt [B_ * N_ * 96];              // 6 MB
__device__ float g_part[NPART * 8];
__device__ float g_stats[8];                       // mean[4], rstd[4]

__device__ __forceinline__ float warp_sum(float v) {
#pragma unroll
    for (int off = 16; off; off >>= 1)
        v += __shfl_xor_sync(FULLMASK, v, off);
    return v;
}

// stable insert into a sorted 16-list living in lanes [base, base+16)
__device__ __forceinline__ void insert_h(float dv, int iv, int lane, int base,
                                         float& ld, int& li, float& cmax)
{
    const unsigned m = __ballot_sync(FULLMASK, ld <= dv);
    const int pos = __popc((m >> base) & 0xFFFFu);      // after equals -> stable
    const float pld = __shfl_up_sync(FULLMASK, ld, 1);
    const int   pli = __shfl_up_sync(FULLMASK, li, 1);
    const int r = lane - base;
    if (r > pos && r < 16) { ld = pld; li = pli; }
    if (r == pos)          { ld = dv;  li = iv;  }
    cmax = __shfl_sync(FULLMASK, ld, base + 15);
}

// =====================================================================
// Kernel 1: KNN — warp serves TWO queries (half-warp sorted lists),
//           2 candidates/lane/step, fused PE-stats partials
// =====================================================================
__global__ __launch_bounds__(512) void knn_kernel(const float4* __restrict__ xytp,
                                                  const float* __restrict__ pe_w1,
                                                  const float* __restrict__ pe_b1)
{
    __shared__ float4 tile[2048];           // 32 KB
    __shared__ float  sred[16 * 8];
    const int b    = blockIdx.y;
    const int tid  = threadIdx.x;
    const int warp = tid >> 5;
    const int lane = tid & 31;
    const int q0   = blockIdx.x * QPB + warp * 2;
    const int q1   = q0 + 1;
    const float4* xp = xytp + (size_t)b * N_;

    const float4 qa = xp[q0];
    const float4 qb = xp[q1];

    float ld    = finf();
    int   li    = 0;
    float cmax0 = finf();
    float cmax1 = finf();

    for (int t = 0; t < 4; ++t) {
        const int base = t * 2048;
        __syncthreads();
        for (int i = tid; i < 2048; i += 512) {
            const float4 v = xp[base + i];
            const float n2 = fmaf(v.z, v.z, fmaf(v.y, v.y, v.x * v.x));
            tile[i] = make_float4(-2.f * v.x, -2.f * v.y, -2.f * v.z, n2);
        }
        __syncthreads();

#pragma unroll 4
        for (int s = 0; s < 32; ++s) {
            const float4 c0 = tile[s * 64 + lane];
            const float4 c1 = tile[s * 64 + 32 + lane];
            const float d00 = fmaf(qa.x, c0.x, fmaf(qa.y, c0.y, fmaf(qa.z, c0.z, c0.w)));
            const float d10 = fmaf(qa.x, c1.x, fmaf(qa.y, c1.y, fmaf(qa.z, c1.z, c1.w)));
            const float d01 = fmaf(qb.x, c0.x, fmaf(qb.y, c0.y, fmaf(qb.z, c0.z, c0.w)));
            const float d11 = fmaf(qb.x, c1.x, fmaf(qb.y, c1.y, fmaf(qb.z, c1.z, c1.w)));
            const bool hit = (fminf(d00, d10) < cmax0) | (fminf(d01, d11) < cmax1);
            if (__ballot_sync(FULLMASK, hit)) {
                const int cb = base + s * 64;
                // ---- query 0: c0 set (ascending idx) then c1 set ----
                unsigned bl = __ballot_sync(FULLMASK, d00 < cmax0);
                while (bl) {
                    const int src = __ffs(bl) - 1; bl &= bl - 1;
                    const float dv = __shfl_sync(FULLMASK, d00, src);
                    if (dv < cmax0) insert_h(dv, cb + src, lane, 0, ld, li, cmax0);
                }
                bl = __ballot_sync(FULLMASK, d10 < cmax0);
                while (bl) {
                    const int src = __ffs(bl) - 1; bl &= bl - 1;
                    const float dv = __shfl_sync(FULLMASK, d10, src);
                    if (dv < cmax0) insert_h(dv, cb + 32 + src, lane, 0, ld, li, cmax0);
                }
                // ---- query 1 ----
                bl = __ballot_sync(FULLMASK, d01 < cmax1);
                while (bl) {
                    const int src = __ffs(bl) - 1; bl &= bl - 1;
                    const float dv = __shfl_sync(FULLMASK, d01, src);
                    if (dv < cmax1) insert_h(dv, cb + src, lane, 16, ld, li, cmax1);
                }
                bl = __ballot_sync(FULLMASK, d11 < cmax1);
                while (bl) {
                    const int src = __ffs(bl) - 1; bl &= bl - 1;
                    const float dv = __shfl_sync(FULLMASK, d11, src);
                    if (dv < cmax1) insert_h(dv, cb + 32 + src, lane, 16, ld, li, cmax1);
                }
            }
        }
    }
    {
        const int qo = (lane < 16) ? q0 : q1;
        g_knn[((size_t)b * N_ + qo) * K_ + (lane & 15)] = li;
    }

    // ---- fused position-encoder stats partials (all 32 lanes hold an entry) ----
    const float4 qo = (lane < 16) ? qa : qb;
    const float4 nb = xp[li];
    const float r0 = qo.x - nb.x, r1 = qo.y - nb.y, r2 = qo.z - nb.z, r3 = qo.w - nb.w;
    float acc[8];
#pragma unroll
    for (int f = 0; f < 4; ++f) {
        float h = pe_b1[f];
        h = fmaf(r0, pe_w1[f * 4 + 0], h);
        h = fmaf(r1, pe_w1[f * 4 + 1], h);
        h = fmaf(r2, pe_w1[f * 4 + 2], h);
        h = fmaf(r3, pe_w1[f * 4 + 3], h);
        acc[f]     = h;
        acc[4 + f] = h * h;
    }
#pragma unroll
    for (int i = 0; i < 8; ++i) acc[i] = warp_sum(acc[i]);
    if (lane == 0) {
#pragma unroll
        for (int i = 0; i < 8; ++i) sred[warp * 8 + i] = acc[i];
    }
    __syncthreads();
    if (tid < 8) {
        float s = 0.f;
#pragma unroll
        for (int w = 0; w < 16; ++w) s += sred[w * 8 + tid];
        g_part[((size_t)blockIdx.y * KNN_BLOCKS + blockIdx.x) * 8 + tid] = s;
    }
}

// =====================================================================
// Kernel 2: lt = features @ lt_w^T + lt_b   (thread per point)
// =====================================================================
__global__ __launch_bounds__(256) void lt_kernel(const float* __restrict__ features,
                                                 const float* __restrict__ lt_w,
                                                 const float* __restrict__ lt_b)
{
    __shared__ float w[96 * 32];
    __shared__ float bias[96];
    for (int i = threadIdx.x; i < 96 * 32; i += 256) w[i] = lt_w[i];
    if (threadIdx.x < 96) bias[threadIdx.x] = lt_b[threadIdx.x];
    __syncthreads();

    const int p = blockIdx.x * 256 + threadIdx.x;
    float4 f4[8];
    const float4* fr = (const float4*)(features + (size_t)p * C_);
#pragma unroll
    for (int i = 0; i < 8; ++i) f4[i] = fr[i];

    float* outp = g_lt + (size_t)p * 96;
#pragma unroll 4
    for (int o = 0; o < 96; ++o) {
        float a = bias[o];
        const float4* wr = (const float4*)(w + o * 32);
#pragma unroll
        for (int i = 0; i < 8; ++i) {
            const float4 wv = wr[i];
            a = fmaf(f4[i].x, wv.x, a);
            a = fmaf(f4[i].y, wv.y, a);
            a = fmaf(f4[i].z, wv.z, a);
            a = fmaf(f4[i].w, wv.w, a);
        }
        outp[o] = a;
    }
}

// =====================================================================
// Kernel 3: finalize stats (parallel, fixed-order => deterministic)
// =====================================================================
__global__ __launch_bounds__(256) void pe_finalize_kernel()
{
    __shared__ float red[32 * 8];
    __shared__ float tot8[8];
    const int t = threadIdx.x;          // 256
    const int ch = t & 7, grp = t >> 3; // 32 groups of (NPART/32) partials
    float s = 0.f;
    const int base = grp * (NPART / 32);
    for (int i = 0; i < NPART / 32; ++i) s += g_part[(base + i) * 8 + ch];
    red[grp * 8 + ch] = s;
    __syncthreads();
    if (t < 8) {
        float tt = 0.f;
        for (int g = 0; g < 32; ++g) tt += red[g * 8 + t];
        tot8[t] = tt;
    }
    __syncthreads();
    if (t < 4) {
        const float invc = 1.f / (float)(B_ * N_ * K_);
        const float mean = tot8[t] * invc;
        const float var  = fmaf(tot8[4 + t], invc, -mean * mean);
        g_stats[t]     = mean;
        g_stats[4 + t] = rsqrtf(var + 1e-5f);
    }
}

// =====================================================================
// Kernel 4: fused main — warp per point, lane = channel
// =====================================================================
__global__ __launch_bounds__(256) void main_kernel(const float4* __restrict__ xytp,
                                                   const float* __restrict__ pe_w1,
                                                   const float* __restrict__ pe_b1,
                                                   const float* __restrict__ pe_gamma,
                                                   const float* __restrict__ pe_beta,
                                                   const float* __restrict__ pe_w2,
                                                   const float* __restrict__ pe_b2,
                                                   const float* __restrict__ ln_gamma,
                                                   const float* __restrict__ ln_beta,
                                                   float* __restrict__ out)
{
    const int warp = threadIdx.x >> 5;
    const int lane = threadIdx.x & 31;
    const int p    = blockIdx.x * 8 + warp;
    const int b    = p >> 13;

    float w1[16], b1v[4], mean[4], rstd[4], gam[4], bet[4], w2a[4];
#pragma unroll
    for (int i = 0; i < 16; ++i) w1[i] = pe_w1[i];
#pragma unroll
    for (int f = 0; f < 4; ++f) {
        b1v[f]  = pe_b1[f];
        mean[f] = g_stats[f];
        rstd[f] = g_stats[4 + f];
        gam[f]  = pe_gamma[f];
        bet[f]  = pe_beta[f];
    }
    {
        const float4 w2 = ((const float4*)pe_w2)[lane];
        w2a[0] = w2.x; w2a[1] = w2.y; w2a[2] = w2.z; w2a[3] = w2.w;
    }
    const float b2 = pe_b2[lane];
    const float lg = ln_gamma[lane];
    const float lb = ln_beta[lane];

    const float  varphi = g_lt[(size_t)p * 96 + lane];
    const float4 q      = xytp[p];
    const int    myidx  = g_knn[(size_t)p * K_ + (lane & 15)];

    float lgt[16], av[16];
#pragma unroll
    for (int k = 0; k < 16; ++k) {
        const int j = __shfl_sync(FULLMASK, myidx, k);
        const float4 nb = xytp[(size_t)b * N_ + j];
        const float r0 = q.x - nb.x, r1 = q.y - nb.y, r2 = q.z - nb.z, r3 = q.w - nb.w;

        float del = b2;
#pragma unroll
        for (int f = 0; f < 4; ++f) {
            float h = b1v[f];
            h = fmaf(r0, w1[f * 4 + 0], h);
            h = fmaf(r1, w1[f * 4 + 1], h);
            h = fmaf(r2, w1[f * 4 + 2], h);
            h = fmaf(r3, w1[f * 4 + 3], h);
            float u = (h - mean[f]) * rstd[f];
            u = fmaf(u, gam[f], bet[f]);
            u = fmaxf(u, 0.f);
            del = fmaf(u, w2a[f], del);
        }

        const size_t row = ((size_t)b * N_ + j) * 96;
        const float psi   = g_lt[row + 32 + lane];
        const float alpha = g_lt[row + 64 + lane];

        const float pre = (varphi - psi) + del;
        const float s1  = warp_sum(pre);
        const float s2  = warp_sum(pre * pre);
        const float mu  = s1 * (1.f / 32.f);
        const float var = fmaf(s2, 1.f / 32.f, -mu * mu);
        const float rs  = rsqrtf(var + 1e-5f);
        lgt[k] = fmaf((pre - mu) * rs, lg, lb);
        av[k]  = alpha + del;
    }

    float m = -finf();
#pragma unroll
    for (int k = 0; k < 16; ++k) m = fmaxf(m, lgt[k]);
    const float inv_scale = 0.17677669529663687f;   // 1/sqrt(32)
    float se = 0.f, acc = 0.f;
#pragma unroll
    for (int k = 0; k < 16; ++k) {
        const float e = __expf((lgt[k] - m) * inv_scale);
        se  += e;
        acc  = fmaf(e, av[k], acc);
    }
    out[(size_t)p * C_ + lane] = acc / se;
}

// =====================================================================
// Launch
// =====================================================================
extern "C" void kernel_launch(void* const* d_in, const int* in_sizes, int n_in,
                              void* d_out, int out_size)
{
    const float* xytp     = (const float*)d_in[0];
    const float* features = (const float*)d_in[1];
    const float* pe_w1    = (const float*)d_in[2];
    const float* pe_b1    = (const float*)d_in[3];
    const float* pe_gamma = (const float*)d_in[4];
    const float* pe_beta  = (const float*)d_in[5];
    const float* pe_w2    = (const float*)d_in[6];
    const float* pe_b2    = (const float*)d_in[7];
    const float* lt_w     = (const float*)d_in[8];
    const float* lt_b     = (const float*)d_in[9];
    const float* ln_gamma = (const float*)d_in[10];
    const float* ln_beta  = (const float*)d_in[11];
    float* out = (float*)d_out;

    knn_kernel<<<dim3(KNN_BLOCKS, B_), 512>>>((const float4*)xytp, pe_w1, pe_b1);
    lt_kernel<<<(B_ * N_) / 256, 256>>>(features, lt_w, lt_b);
    pe_finalize_kernel<<<1, 256>>>();
    main_kernel<<<(B_ * N_) / 8, 256>>>((const float4*)xytp, pe_w1, pe_b1,
                                        pe_gamma, pe_beta, pe_w2, pe_b2,
                                        ln_gamma, ln_beta, out);
}